// round 5
// baseline (speedup 1.0000x reference)
#include <cuda_runtime.h>

#define B 64
#define CHI 20
#define D 65536          // 64*32*32 elements per frame
#define WAVE 8           // batches per wave (42 MB -> two waves fit in 126 MB L2)
#define NWAVES (B / WAVE)
#define NSPLIT 4
#define CHUNK (D / NSPLIT)          // 16384 floats per score block
#define SCORE_BLKS (WAVE * CHI * NSPLIT)   // 640
#define OUT_BLKS (WAVE * (D / 256))        // 2048
#define GROUP_SZ 21                  // 5 score + 16 out blocks interleaved
#define N_GROUPS (SCORE_BLKS / 5)    // 128 ; 128*21 = 2688 = 640+2048

// partial pre-softmax scores: [B][CHI][NSPLIT]
__device__ float g_partial[B * CHI * NSPLIT];

// ---------------------------------------------------------------------------
// score block: partial[b][c][split] = sum over CHUNK of frame_c * frame_19
// ---------------------------------------------------------------------------
__device__ __forceinline__ void score_block(const float* __restrict__ x,
                                            float* __restrict__ partial,
                                            int sw, int idx) {
    const int split = idx & (NSPLIT - 1);
    const int c     = (idx >> 2) % CHI;
    const int bw    = idx / (CHI * NSPLIT);
    const int b     = sw * WAVE + bw;

    const float4* __restrict__ fr = reinterpret_cast<const float4*>(
        x + (size_t)(b * CHI + c) * D + (size_t)split * CHUNK);
    const float4* __restrict__ la = reinterpret_cast<const float4*>(
        x + (size_t)(b * CHI + (CHI - 1)) * D + (size_t)split * CHUNK);

    const int tid = threadIdx.x;
    float acc = 0.0f;
    #pragma unroll
    for (int i = 0; i < CHUNK / 4 / 256; i++) {    // 16 iterations
        const int j = i * 256 + tid;
        float4 f = fr[j];
        float4 l = la[j];
        acc = fmaf(f.x, l.x, acc);
        acc = fmaf(f.y, l.y, acc);
        acc = fmaf(f.z, l.z, acc);
        acc = fmaf(f.w, l.w, acc);
    }

    #pragma unroll
    for (int o = 16; o; o >>= 1) acc += __shfl_xor_sync(0xFFFFFFFFu, acc, o);

    __shared__ float sred[8];
    const int warp = tid >> 5;
    const int lane = tid & 31;
    if (lane == 0) sred[warp] = acc;
    __syncthreads();
    if (warp == 0) {
        acc = (lane < 8) ? sred[lane] : 0.0f;
        #pragma unroll
        for (int o = 4; o; o >>= 1) acc += __shfl_xor_sync(0xFFFFFFFFu, acc, o);
        if (lane == 0)
            partial[(b * CHI + c) * NSPLIT + split] = acc;
    }
}

// ---------------------------------------------------------------------------
// out block: out[b,d] = sum_c x_dmajor[b,d,c] * alpha[b,c]
// softmax recomputed per block from g_partial (written by previous launch).
// ---------------------------------------------------------------------------
__device__ __forceinline__ void out_block(const float* __restrict__ x,
                                          const float* __restrict__ partial,
                                          float* __restrict__ out,
                                          int ow, int idx) {
    const int bw   = idx >> 8;       // / 256
    const int dblk = idx & 255;
    const int b    = ow * WAVE + bw;
    const int tid  = threadIdx.x;

    __shared__ float alpha[CHI];
    if (tid == 0) {
        float s[CHI];
        float m = -1e30f;
        #pragma unroll
        for (int c = 0; c < CHI; c++) {
            const float* p = partial + (b * CHI + c) * NSPLIT;
            float v = ((p[0] + p[1]) + (p[2] + p[3])) * (1.0f / CHI);
            s[c] = v;
            m = fmaxf(m, v);
        }
        float sum = 0.0f;
        #pragma unroll
        for (int c = 0; c < CHI; c++) {
            s[c] = expf(s[c] - m);
            sum += s[c];
        }
        const float inv = 1.0f / sum;
        #pragma unroll
        for (int c = 0; c < CHI; c++) alpha[c] = s[c] * inv;
    }
    __syncthreads();

    float a[CHI];
    #pragma unroll
    for (int c = 0; c < CHI; c++) a[c] = alpha[c];

    const int d = dblk * 256 + tid;
    const float4* __restrict__ p = reinterpret_cast<const float4*>(
        x + (size_t)b * CHI * D + (size_t)d * CHI);

    float acc = 0.0f;
    #pragma unroll
    for (int i = 0; i < 5; i++) {
        float4 v = p[i];
        acc = fmaf(v.x, a[4 * i + 0], acc);
        acc = fmaf(v.y, a[4 * i + 1], acc);
        acc = fmaf(v.z, a[4 * i + 2], acc);
        acc = fmaf(v.w, a[4 * i + 3], acc);
    }
    out[(size_t)b * D + d] = acc;
}

// ---------------------------------------------------------------------------
// fused pipeline kernel: out-phase for wave `ow` runs concurrently with
// score-phase for wave `sw` (either may be -1 for the pipeline edges).
// Block roles interleaved 5:16 so both phases occupy the chip together.
// ---------------------------------------------------------------------------
__global__ __launch_bounds__(256) void fused_kernel(const float* __restrict__ x,
                                                    float* __restrict__ partial,
                                                    float* __restrict__ out,
                                                    int ow, int sw) {
    const int bid = blockIdx.x;
    if (ow < 0) {                       // scores only
        score_block(x, partial, sw, bid);
    } else if (sw < 0) {                // out only
        out_block(x, partial, out, ow, bid);
    } else {
        const int g = bid / GROUP_SZ;
        const int r = bid % GROUP_SZ;
        if (r < 5) score_block(x, partial, sw, g * 5 + r);
        else       out_block(x, partial, out, ow, g * 16 + (r - 5));
    }
}

extern "C" void kernel_launch(void* const* d_in, const int* in_sizes, int n_in,
                              void* d_out, int out_size) {
    const float* x = (const float*)d_in[0];
    float* out = (float*)d_out;

    float* partial;
    cudaGetSymbolAddress((void**)&partial, g_partial);

    // prologue: scores for wave 0
    fused_kernel<<<SCORE_BLKS, 256>>>(x, partial, out, -1, 0);
    // steady state: out(w) overlapped with scores(w+1)
    for (int w = 0; w < NWAVES - 1; w++)
        fused_kernel<<<N_GROUPS * GROUP_SZ, 256>>>(x, partial, out, w, w + 1);
    // epilogue: out for last wave
    fused_kernel<<<OUT_BLKS, 256>>>(x, partial, out, NWAVES - 1, -1);
}

// round 7
// speedup vs baseline: 1.2180x; 1.2180x over previous
#include <cuda_runtime.h>
#include <math.h>

#define B 64
#define CHI 20
#define D 65536                 // 64*32*32 floats per frame
#define D4 (D / 4)              // 16384 float4 per frame

// ---- scores kernel geometry ----
#define NSPLIT 16
#define CHUNK (D / NSPLIT)      // 4096 floats
#define CHUNK4 (CHUNK / 4)      // 1024 float4
#define CGRP 5                  // c's per block
#define NCG (CHI / CGRP)        // 4

// scratch
__device__ float g_partial[B * CHI * NSPLIT];   // pre-softmax partial dots
__device__ float g_alpha[B * CHI];              // softmax weights

// ---------------------------------------------------------------------------
// Kernel 1: partial[b][c][split] = sum_chunk frames[b,c,:] . frames[b,19,:]
// frames = x viewed as [B][CHI][D]. Block = (b, split, group of 5 c's).
// Per iter: 1 'last' load + 5 frame loads, all coalesced float4.
// ---------------------------------------------------------------------------
__global__ __launch_bounds__(256) void scores_kernel(const float* __restrict__ x,
                                                     float* __restrict__ partial) {
    const int bid   = blockIdx.x;
    const int b     = bid / (NSPLIT * NCG);
    const int rem   = bid % (NSPLIT * NCG);
    const int split = rem % NSPLIT;
    const int cg    = rem / NSPLIT;
    const int c0    = cg * CGRP;

    const size_t frame_base = (size_t)b * CHI * D + (size_t)split * CHUNK;
    const float4* __restrict__ la =
        reinterpret_cast<const float4*>(x + frame_base + (size_t)(CHI - 1) * D);
    const float4* __restrict__ f0 =
        reinterpret_cast<const float4*>(x + frame_base + (size_t)c0 * D);

    const int tid = threadIdx.x;
    float acc[CGRP] = {0.f, 0.f, 0.f, 0.f, 0.f};

    #pragma unroll
    for (int i = 0; i < CHUNK4 / 256; i++) {       // 4 iterations
        const int j = i * 256 + tid;
        const float4 l = la[j];
        #pragma unroll
        for (int k = 0; k < CGRP; k++) {
            const float4 f = f0[(size_t)k * D4 + j];
            acc[k] = fmaf(f.x, l.x, acc[k]);
            acc[k] = fmaf(f.y, l.y, acc[k]);
            acc[k] = fmaf(f.z, l.z, acc[k]);
            acc[k] = fmaf(f.w, l.w, acc[k]);
        }
    }

    // warp reduce each accumulator
    #pragma unroll
    for (int k = 0; k < CGRP; k++) {
        #pragma unroll
        for (int o = 16; o; o >>= 1) acc[k] += __shfl_xor_sync(0xFFFFFFFFu, acc[k], o);
    }

    __shared__ float sred[CGRP][8];
    const int warp = tid >> 5;
    const int lane = tid & 31;
    if (lane == 0) {
        #pragma unroll
        for (int k = 0; k < CGRP; k++) sred[k][warp] = acc[k];
    }
    __syncthreads();

    // warps 0..4 each finish one accumulator
    if (warp < CGRP) {
        float v = (lane < 8) ? sred[warp][lane] : 0.0f;
        #pragma unroll
        for (int o = 4; o; o >>= 1) v += __shfl_xor_sync(0xFFFFFFFFu, v, o);
        if (lane == 0)
            partial[((b * CHI) + (c0 + warp)) * NSPLIT + split] = v;
    }
}

// ---------------------------------------------------------------------------
// Kernel 2: alpha[b][c] = softmax_c( sum_split partial[b][c][split] / CHI )
// One warp per batch; lane = c.
// ---------------------------------------------------------------------------
__global__ __launch_bounds__(32) void softmax_kernel(const float* __restrict__ partial,
                                                     float* __restrict__ alpha) {
    const int b = blockIdx.x;
    const int lane = threadIdx.x;

    float s = -INFINITY;
    if (lane < CHI) {
        const float* p = partial + (b * CHI + lane) * NSPLIT;
        float t = 0.0f;
        #pragma unroll
        for (int i = 0; i < NSPLIT; i++) t += p[i];
        s = t * (1.0f / CHI);
    }

    float m = s;
    #pragma unroll
    for (int o = 16; o; o >>= 1) m = fmaxf(m, __shfl_xor_sync(0xFFFFFFFFu, m, o));

    float e = (lane < CHI) ? expf(s - m) : 0.0f;
    float sum = e;
    #pragma unroll
    for (int o = 16; o; o >>= 1) sum += __shfl_xor_sync(0xFFFFFFFFu, sum, o);

    if (lane < CHI) alpha[b * CHI + lane] = e / sum;
}

// ---------------------------------------------------------------------------
// Kernel 3: out[b,d] = sum_c x_flat[b, d*CHI + c] * alpha[b,c]
// (x reinterpreted as [B][D][CHI] — the reference's reshape, NOT a transpose.)
// SMEM staging: block loads its contiguous 20KB region with coalesced
// LDG.128, each thread then reads its own 20 floats via 5 conflict-free
// LDS.128 (stride 80B tiles all 32 banks per 8-lane phase).
// Grid: B * 256 blocks of 256 threads; each block covers 256 d's.
// ---------------------------------------------------------------------------
__global__ __launch_bounds__(256) void out_kernel(const float* __restrict__ x,
                                                  const float* __restrict__ alpha,
                                                  float* __restrict__ out) {
    const int b    = blockIdx.x >> 8;
    const int dblk = blockIdx.x & 255;
    const int tid  = threadIdx.x;

    __shared__ float4 s4[256 * CHI / 4];   // 1280 float4 = 20 KB
    __shared__ float a_s[CHI];
    if (tid < CHI) a_s[tid] = alpha[b * CHI + tid];

    const float4* __restrict__ src = reinterpret_cast<const float4*>(
        x + (size_t)b * CHI * D + (size_t)dblk * 256 * CHI);

    #pragma unroll
    for (int i = 0; i < 5; i++)
        s4[i * 256 + tid] = src[i * 256 + tid];
    __syncthreads();

    float a[CHI];
    #pragma unroll
    for (int c = 0; c < CHI; c++) a[c] = a_s[c];

    const float4* mine = s4 + tid * 5;     // this thread's 20 contiguous floats
    float acc = 0.0f;
    #pragma unroll
    for (int i = 0; i < 5; i++) {
        const float4 v = mine[i];
        acc = fmaf(v.x, a[4 * i + 0], acc);
        acc = fmaf(v.y, a[4 * i + 1], acc);
        acc = fmaf(v.z, a[4 * i + 2], acc);
        acc = fmaf(v.w, a[4 * i + 3], acc);
    }

    out[(size_t)b * D + dblk * 256 + tid] = acc;
}

extern "C" void kernel_launch(void* const* d_in, const int* in_sizes, int n_in,
                              void* d_out, int out_size) {
    const float* x = (const float*)d_in[0];
    float* out = (float*)d_out;

    float *partial, *alpha;
    cudaGetSymbolAddress((void**)&partial, g_partial);
    cudaGetSymbolAddress((void**)&alpha, g_alpha);

    scores_kernel<<<B * NSPLIT * NCG, 256>>>(x, partial);
    softmax_kernel<<<B, 32>>>(partial, alpha);
    out_kernel<<<B * 256, 256>>>(x, alpha, out);
}